// round 1
// baseline (speedup 1.0000x reference)
#include <cuda_runtime.h>
#include <math.h>

#define NTOK 2048
#define CDIM 1024
#define IDIM 4096
#define NEXP 8
#define HR   256   // router hidden = C/4

// ---------------- scratch (__device__ globals; no allocation allowed) --------
__device__ int   g_count[NEXP];
__device__ int   g_cursor[NEXP];
__device__ int   g_base[NEXP];
__device__ int   g_row_tok[NTOK * 2];   // global row -> token index
__device__ int   g_row_of[NTOK * 2];    // token,k -> global row
__device__ int   g_tok_eidx[NTOK * 2];  // token,k -> expert
__device__ float g_tok_w[NTOK * 2];     // token,k -> combine weight
__device__ float g_hbuf[(size_t)NTOK * 2 * IDIM];  // 64 MB expert hidden
__device__ float g_ybuf[(size_t)NTOK * 2 * CDIM];  // 16 MB expert out rows
__device__ float g_hs[(size_t)NTOK * IDIM];        // 32 MB shared hidden

// ---------------- init ------------------------------------------------------
__global__ void init_k() {
    int t = threadIdx.x;
    if (t < NEXP) { g_count[t] = 0; g_cursor[t] = 0; }
}

// ---------------- router: one block per token -------------------------------
__global__ void router_k(const float* __restrict__ x,
                         const float* __restrict__ rw1, const float* __restrict__ rb1,
                         const float* __restrict__ rw2, const float* __restrict__ rb2) {
    __shared__ float xs[CDIM];
    __shared__ float hs[HR];
    __shared__ float lg[NEXP];
    int n = blockIdx.x, t = threadIdx.x;
    const float* xr = x + (size_t)n * CDIM;
    for (int c = t; c < CDIM; c += 256) xs[c] = xr[c];
    __syncthreads();
    // hidden[t] = relu(x . rw1[:,t] + rb1[t]); rw1 is (C, HR) row-major
    float acc = rb1[t];
    #pragma unroll 4
    for (int c = 0; c < CDIM; c++) acc += xs[c] * rw1[(size_t)c * HR + t];
    hs[t] = fmaxf(acc, 0.0f);
    __syncthreads();
    int w = t >> 5, l = t & 31;
    if (w < NEXP) {
        float p = 0.0f;
        for (int h = l; h < HR; h += 32) p += hs[h] * rw2[(size_t)h * NEXP + w];
        #pragma unroll
        for (int o = 16; o; o >>= 1) p += __shfl_down_sync(0xffffffffu, p, o);
        if (l == 0) lg[w] = p + rb2[w];
    }
    __syncthreads();
    if (t == 0) {
        float mx = lg[0];
        for (int e = 1; e < NEXP; e++) mx = fmaxf(mx, lg[e]);
        float ge[NEXP]; float s = 0.0f;
        for (int e = 0; e < NEXP; e++) { ge[e] = expf(lg[e] - mx); s += ge[e]; }
        for (int e = 0; e < NEXP; e++) ge[e] /= s;
        // top-2 (ties -> lowest index, matching lax.top_k)
        int i0 = 0;
        for (int e = 1; e < NEXP; e++) if (ge[e] > ge[i0]) i0 = e;
        int i1 = -1;
        for (int e = 0; e < NEXP; e++) {
            if (e == i0) continue;
            if (i1 < 0 || ge[e] > ge[i1]) i1 = e;
        }
        // re-softmax of (gate / TOP_K)
        float a = expf(ge[i0] * 0.5f), b = expf(ge[i1] * 0.5f);
        float inv = 1.0f / (a + b);
        g_tok_eidx[n * 2]     = i0;  g_tok_eidx[n * 2 + 1] = i1;
        g_tok_w[n * 2]        = a * inv;
        g_tok_w[n * 2 + 1]    = b * inv;
        atomicAdd(&g_count[i0], 1);
        atomicAdd(&g_count[i1], 1);
    }
}

__global__ void scan_k() {
    if (threadIdx.x == 0) {
        int s = 0;
        for (int e = 0; e < NEXP; e++) { g_base[e] = s; s += g_count[e]; }
    }
}

__global__ void fill_k() {
    int n = blockIdx.x * blockDim.x + threadIdx.x;
    if (n >= NTOK) return;
    #pragma unroll
    for (int k = 0; k < 2; k++) {
        int e = g_tok_eidx[n * 2 + k];
        int slot = atomicAdd(&g_cursor[e], 1);
        int row = g_base[e] + slot;
        g_row_tok[row] = n;
        g_row_of[n * 2 + k] = row;
    }
}

// ---------------- tiled fp32 GEMM ------------------------------------------
// C[M,Nd] = act(A[M,K] @ Bw[K,Nd] + bias[Nd])
// EXPERT: blockIdx.z selects expert; M=g_count[e], rows offset by g_base[e],
//         Bw/bias offset by expert stride.
// GATHER: A row index comes from g_row_tok (gather token rows of x).
template<bool EXPERT, bool GATHER, bool SILU>
__global__ void gemm_k(const float* __restrict__ A, const float* __restrict__ Bw,
                       const float* __restrict__ bias, float* __restrict__ Cm,
                       int M, int K, int Nd) {
    const int BM = 64, BN = 64, BK = 16;
    __shared__ float As[BK][68];   // padded stride (68*4B, 16B aligned rows)
    __shared__ float Bs[BK][BN];

    int rowbase = 0;
    if (EXPERT) {
        int e = blockIdx.z;
        M = g_count[e];
        rowbase = g_base[e];
        Bw   += (size_t)e * K * Nd;
        bias += (size_t)e * Nd;
    }
    int m0 = blockIdx.y * BM;
    if (m0 >= M) return;
    int n0 = blockIdx.x * BN;
    int t  = threadIdx.x;          // 256 threads
    int tx = t & 15, ty = t >> 4;

    // A loading role: row lr (0..63), float4 quad q (0..3)
    int lr = t >> 2, q = t & 3;
    int arow = m0 + lr;
    bool avalid = arow < M;
    const float* aptr = A;  // dummy
    if (avalid) {
        int grow = rowbase + arow;
        int srcrow = GATHER ? g_row_tok[grow] : grow;
        aptr = A + (size_t)srcrow * K + 4 * q;
    }
    // B loading role: row bkrow (0..15), float4 col bq (0..15)
    int bkrow = t >> 4, bq = t & 15;

    float acc[4][4];
    #pragma unroll
    for (int i = 0; i < 4; i++)
        #pragma unroll
        for (int j = 0; j < 4; j++) acc[i][j] = 0.0f;

    for (int k0 = 0; k0 < K; k0 += BK) {
        float4 av = avalid ? *(const float4*)(aptr + k0) : make_float4(0, 0, 0, 0);
        As[4 * q + 0][lr] = av.x;
        As[4 * q + 1][lr] = av.y;
        As[4 * q + 2][lr] = av.z;
        As[4 * q + 3][lr] = av.w;
        float4 bv = *(const float4*)(Bw + (size_t)(k0 + bkrow) * Nd + n0 + 4 * bq);
        *(float4*)&Bs[bkrow][4 * bq] = bv;
        __syncthreads();
        #pragma unroll
        for (int kk = 0; kk < BK; kk++) {
            float4 a4 = *(const float4*)&As[kk][ty * 4];
            float4 b4 = *(const float4*)&Bs[kk][tx * 4];
            float aa[4] = {a4.x, a4.y, a4.z, a4.w};
            float bb[4] = {b4.x, b4.y, b4.z, b4.w};
            #pragma unroll
            for (int i = 0; i < 4; i++)
                #pragma unroll
                for (int j = 0; j < 4; j++) acc[i][j] += aa[i] * bb[j];
        }
        __syncthreads();
    }

    #pragma unroll
    for (int i = 0; i < 4; i++) {
        int r = m0 + ty * 4 + i;
        if (r >= M) continue;
        int crow = rowbase + r;
        float* cp = Cm + (size_t)crow * Nd + n0 + tx * 4;
        #pragma unroll
        for (int j = 0; j < 4; j++) {
            float v = acc[i][j] + bias[n0 + tx * 4 + j];
            if (SILU) v = v / (1.0f + __expf(-v));
            cp[j] = v;
        }
    }
}

// ---------------- combine ----------------------------------------------------
__global__ void combine_k(const float* __restrict__ y, float* __restrict__ out) {
    int n = blockIdx.x;
    int r0 = g_row_of[n * 2], r1 = g_row_of[n * 2 + 1];
    float w0 = g_tok_w[n * 2], w1 = g_tok_w[n * 2 + 1];
    const float* y0 = y + (size_t)r0 * CDIM;
    const float* y1 = y + (size_t)r1 * CDIM;
    float* o = out + (size_t)n * CDIM;
    for (int c = threadIdx.x; c < CDIM; c += blockDim.x)
        o[c] += w0 * y0[c] + w1 * y1[c];
}

// ---------------- launch -----------------------------------------------------
extern "C" void kernel_launch(void* const* d_in, const int* in_sizes, int n_in,
                              void* d_out, int out_size) {
    const float* x   = (const float*)d_in[0];
    const float* rw1 = (const float*)d_in[1];
    const float* rb1 = (const float*)d_in[2];
    const float* rw2 = (const float*)d_in[3];
    const float* rb2 = (const float*)d_in[4];
    const float* ew1 = (const float*)d_in[5];
    const float* eb1 = (const float*)d_in[6];
    const float* ew2 = (const float*)d_in[7];
    const float* eb2 = (const float*)d_in[8];
    const float* sw1 = (const float*)d_in[9];
    const float* sb1 = (const float*)d_in[10];
    const float* sw2 = (const float*)d_in[11];
    const float* sb2 = (const float*)d_in[12];
    float* out = (float*)d_out;

    float *hbuf, *ybuf, *hsbuf;
    cudaGetSymbolAddress((void**)&hbuf,  g_hbuf);
    cudaGetSymbolAddress((void**)&ybuf,  g_ybuf);
    cudaGetSymbolAddress((void**)&hsbuf, g_hs);

    init_k<<<1, 32>>>();
    router_k<<<NTOK, 256>>>(x, rw1, rb1, rw2, rb2);
    scan_k<<<1, 32>>>();
    fill_k<<<(NTOK + 255) / 256, 256>>>();

    // shared expert: hs = silu(x @ sw1 + sb1); out = hs @ sw2 + sb2
    {
        dim3 g1(IDIM / 64, NTOK / 64);
        gemm_k<false, false, true><<<g1, 256>>>(x, sw1, sb1, hsbuf, NTOK, CDIM, IDIM);
        dim3 g2(CDIM / 64, NTOK / 64);
        gemm_k<false, false, false><<<g2, 256>>>(hsbuf, sw2, sb2, out, NTOK, IDIM, CDIM);
    }
    // routed experts: h = silu(gather(x) @ ew1[e] + eb1[e]); y = h @ ew2[e] + eb2[e]
    {
        dim3 g1(IDIM / 64, NTOK / 64, NEXP);   // worst case: one expert gets all tokens
        gemm_k<true, true, true><<<g1, 256>>>(x, ew1, eb1, hbuf, 0, CDIM, IDIM);
        dim3 g2(CDIM / 64, NTOK / 64, NEXP);
        gemm_k<true, false, false><<<g2, 256>>>(hbuf, ew2, eb2, ybuf, 0, IDIM, CDIM);
    }
    combine_k<<<NTOK, 256>>>(ybuf, out);
}

// round 3
// speedup vs baseline: 3.0099x; 3.0099x over previous
#include <cuda_runtime.h>
#include <math.h>
#include <stdint.h>

#define NTOK 2048
#define CDIM 1024
#define IDIM 4096
#define NEXP 8
#define HR   256

#define BM 128
#define BN 128
#define BK 32
#define THREADS 256

// smem (floats): A buffers 128x36, B buffers 32x132, double buffered
#define A_ST 36
#define B_ST 132
#define AB0  0
#define AB1  4608
#define BB0  9216
#define BB1  13440
#define SMEM_BYTES (17664 * 4)

// ---------------- scratch ----------------------------------------------------
__device__ int   g_count[NEXP];
__device__ int   g_cursor[NEXP];
__device__ int   g_base[NEXP];
__device__ int   g_row_tok[NTOK * 2];
__device__ int   g_row_of[NTOK * 2];
__device__ int   g_tok_eidx[NTOK * 2];
__device__ float g_tok_w[NTOK * 2];
__device__ float g_hbuf[(size_t)NTOK * 2 * IDIM];     // 64 MB expert hidden
__device__ float g_ybuf[(size_t)NTOK * 2 * CDIM];     // 16 MB expert out
__device__ float g_hs[(size_t)NTOK * IDIM];           // 32 MB shared hidden
__device__ float g_xr[(size_t)NTOK * CDIM];           // 8 MB rounded x
__device__ float g_ew1r[(size_t)NEXP * CDIM * IDIM];  // 134 MB rounded ew1
__device__ float g_ew2r[(size_t)NEXP * IDIM * CDIM];  // 134 MB rounded ew2
__device__ float g_sw1r[(size_t)CDIM * IDIM];         // 16.8 MB rounded sw1
__device__ float g_sw2r[(size_t)IDIM * CDIM];         // 16.8 MB rounded sw2

// ---------------- helpers ----------------------------------------------------
__device__ __forceinline__ uint32_t smem_u32(const void* p) {
    uint32_t a;
    asm("{ .reg .u64 t; cvta.to.shared.u64 t, %1; cvt.u32.u64 %0, t; }" : "=r"(a) : "l"(p));
    return a;
}
__device__ __forceinline__ float rna_tf32(float f) {
    uint32_t u;
    asm("cvt.rna.tf32.f32 %0, %1;" : "=r"(u) : "f"(f));
    return __uint_as_float(u);
}
__device__ __forceinline__ void cp16(uint32_t dst, const float* src) {
    asm volatile("cp.async.cg.shared.global [%0], [%1], 16;" :: "r"(dst), "l"(src) : "memory");
}
__device__ __forceinline__ void cp_commit() {
    asm volatile("cp.async.commit_group;" ::: "memory");
}
template<int N> __device__ __forceinline__ void cp_wait() {
    asm volatile("cp.async.wait_group %0;" :: "n"(N) : "memory");
}
__device__ __forceinline__ void mma8(float* c, const uint32_t* a, const uint32_t* b) {
    asm volatile(
        "mma.sync.aligned.m16n8k8.row.col.f32.tf32.tf32.f32 "
        "{%0,%1,%2,%3}, {%4,%5,%6,%7}, {%8,%9}, {%0,%1,%2,%3};"
        : "+f"(c[0]), "+f"(c[1]), "+f"(c[2]), "+f"(c[3])
        : "r"(a[0]), "r"(a[1]), "r"(a[2]), "r"(a[3]), "r"(b[0]), "r"(b[1]));
}

// ---------------- init / router / routing (unchanged logic) ------------------
__global__ void init_k() {
    int t = threadIdx.x;
    if (t < NEXP) { g_count[t] = 0; g_cursor[t] = 0; }
}

__global__ void router_k(const float* __restrict__ x,
                         const float* __restrict__ rw1, const float* __restrict__ rb1,
                         const float* __restrict__ rw2, const float* __restrict__ rb2) {
    __shared__ float xs[CDIM];
    __shared__ float hs[HR];
    __shared__ float lg[NEXP];
    int n = blockIdx.x, t = threadIdx.x;
    const float* xr = x + (size_t)n * CDIM;
    for (int c = t; c < CDIM; c += 256) xs[c] = xr[c];
    __syncthreads();
    float acc = rb1[t];
    #pragma unroll 4
    for (int c = 0; c < CDIM; c++) acc += xs[c] * rw1[(size_t)c * HR + t];
    hs[t] = fmaxf(acc, 0.0f);
    __syncthreads();
    int w = t >> 5, l = t & 31;
    if (w < NEXP) {
        float p = 0.0f;
        for (int h = l; h < HR; h += 32) p += hs[h] * rw2[(size_t)h * NEXP + w];
        #pragma unroll
        for (int o = 16; o; o >>= 1) p += __shfl_down_sync(0xffffffffu, p, o);
        if (l == 0) lg[w] = p + rb2[w];
    }
    __syncthreads();
    if (t == 0) {
        float mx = lg[0];
        for (int e = 1; e < NEXP; e++) mx = fmaxf(mx, lg[e]);
        float ge[NEXP]; float s = 0.0f;
        for (int e = 0; e < NEXP; e++) { ge[e] = expf(lg[e] - mx); s += ge[e]; }
        for (int e = 0; e < NEXP; e++) ge[e] /= s;
        int i0 = 0;
        for (int e = 1; e < NEXP; e++) if (ge[e] > ge[i0]) i0 = e;
        int i1 = -1;
        for (int e = 0; e < NEXP; e++) {
            if (e == i0) continue;
            if (i1 < 0 || ge[e] > ge[i1]) i1 = e;
        }
        float a = expf(ge[i0] * 0.5f), b = expf(ge[i1] * 0.5f);
        float inv = 1.0f / (a + b);
        g_tok_eidx[n * 2] = i0;  g_tok_eidx[n * 2 + 1] = i1;
        g_tok_w[n * 2] = a * inv;
        g_tok_w[n * 2 + 1] = b * inv;
        atomicAdd(&g_count[i0], 1);
        atomicAdd(&g_count[i1], 1);
    }
}

__global__ void scan_k() {
    if (threadIdx.x == 0) {
        int s = 0;
        for (int e = 0; e < NEXP; e++) { g_base[e] = s; s += g_count[e]; }
    }
}

__global__ void fill_k() {
    int n = blockIdx.x * blockDim.x + threadIdx.x;
    if (n >= NTOK) return;
    #pragma unroll
    for (int k = 0; k < 2; k++) {
        int e = g_tok_eidx[n * 2 + k];
        int slot = atomicAdd(&g_cursor[e], 1);
        int row = g_base[e] + slot;
        g_row_tok[row] = n;
        g_row_of[n * 2 + k] = row;
    }
}

// ---------------- tf32 rounding pass ----------------------------------------
__global__ void round_k(const float4* __restrict__ in, float4* __restrict__ out, int n4) {
    int i = blockIdx.x * blockDim.x + threadIdx.x;
    if (i >= n4) return;
    float4 v = in[i];
    v.x = rna_tf32(v.x); v.y = rna_tf32(v.y);
    v.z = rna_tf32(v.z); v.w = rna_tf32(v.w);
    out[i] = v;
}

// ---------------- tf32 mma.sync GEMM -----------------------------------------
// C[M,Nd] = act(A[M,K] @ Bw[K,Nd] + bias); Bw row-major [K,Nd] (original layout).
template<bool EXPERT, bool GATHER, bool SILU>
__global__ void __launch_bounds__(THREADS, 2) tgemm_k(
    const float* __restrict__ A, const float* __restrict__ Bw,
    const float* __restrict__ bias, float* __restrict__ Cm,
    int M, int K, int Nd)
{
    extern __shared__ float sm[];
    int rowbase = 0;
    if (EXPERT) {
        int e = blockIdx.z;
        M = g_count[e];
        rowbase = g_base[e];
        Bw   += (size_t)e * K * Nd;
        bias += (size_t)e * Nd;
    }
    int m0 = blockIdx.y * BM;
    if (m0 >= M) return;
    int n0 = blockIdx.x * BN;
    int t = threadIdx.x;
    int wid = t >> 5, lane = t & 31;
    int g = lane >> 2, tig = lane & 3;
    int mw = (wid & 1) * 64, nw = (wid >> 1) * 32;
    uint32_t sbase = smem_u32(sm);

    // ---- load roles ----
    // A: 1024 chunks of 16B: chunk idx = t + 256*i  -> row idx>>3, quad idx&7
    const float* asrc[4]; uint32_t aoff[4];
    #pragma unroll
    for (int i = 0; i < 4; i++) {
        int idx = t + THREADS * i;
        int r = idx >> 3, q = idx & 7;
        int rr = m0 + r;
        int rc = rr < M ? rr : (M - 1);
        int src = GATHER ? g_row_tok[rowbase + rc] : (EXPERT ? (rowbase + rc) : rc);
        asrc[i] = A + (size_t)src * K + q * 4;
        aoff[i] = (uint32_t)((r * A_ST + q * 4) * 4);
    }
    // B: 1024 chunks: row idx>>5 (k 0..31), quad idx&31
    const float* bsrc[4]; uint32_t boff[4];
    #pragma unroll
    for (int i = 0; i < 4; i++) {
        int idx = t + THREADS * i;
        int r = idx >> 5, q = idx & 31;
        bsrc[i] = Bw + (size_t)r * Nd + n0 + q * 4;
        boff[i] = (uint32_t)((r * B_ST + q * 4) * 4);
    }

    float c[4][4][4];
    #pragma unroll
    for (int mf = 0; mf < 4; mf++)
        #pragma unroll
        for (int nf = 0; nf < 4; nf++)
            #pragma unroll
            for (int i = 0; i < 4; i++) c[mf][nf][i] = 0.0f;

    int iters = K / BK;
    // prologue: buffer 0
    #pragma unroll
    for (int i = 0; i < 4; i++) cp16(sbase + AB0 * 4 + aoff[i], asrc[i]);
    #pragma unroll
    for (int i = 0; i < 4; i++) cp16(sbase + BB0 * 4 + boff[i], bsrc[i]);
    cp_commit();

    for (int it = 0; it < iters; it++) {
        int buf = it & 1;
        if (it + 1 < iters) {
            int k1 = (it + 1) * BK;
            uint32_t ab = (buf ? AB0 : AB1) * 4, bb = (buf ? BB0 : BB1) * 4;
            #pragma unroll
            for (int i = 0; i < 4; i++) cp16(sbase + ab + aoff[i], asrc[i] + k1);
            #pragma unroll
            for (int i = 0; i < 4; i++) cp16(sbase + bb + boff[i], bsrc[i] + (size_t)k1 * Nd);
            cp_commit();
            cp_wait<1>();
        } else {
            cp_wait<0>();
        }
        __syncthreads();

        const float* Ab = sm + (buf ? AB1 : AB0);
        const float* Bb = sm + (buf ? BB1 : BB0);
        #pragma unroll
        for (int ks = 0; ks < 4; ks++) {
            uint32_t a[4][4], b[4][2];
            #pragma unroll
            for (int mf = 0; mf < 4; mf++) {
                const float* ap = Ab + (mw + mf * 16 + g) * A_ST + ks * 8 + tig;
                a[mf][0] = __float_as_uint(ap[0]);
                a[mf][1] = __float_as_uint(ap[8 * A_ST]);
                a[mf][2] = __float_as_uint(ap[4]);
                a[mf][3] = __float_as_uint(ap[8 * A_ST + 4]);
            }
            #pragma unroll
            for (int nf = 0; nf < 4; nf++) {
                const float* bp = Bb + (ks * 8 + tig) * B_ST + nw + nf * 8 + g;
                b[nf][0] = __float_as_uint(bp[0]);
                b[nf][1] = __float_as_uint(bp[4 * B_ST]);
            }
            #pragma unroll
            for (int mf = 0; mf < 4; mf++)
                #pragma unroll
                for (int nf = 0; nf < 4; nf++)
                    mma8(c[mf][nf], a[mf], b[nf]);
        }
        __syncthreads();
    }

    // ---- epilogue ----
    int outbase = EXPERT ? rowbase : 0;
    #pragma unroll
    for (int mf = 0; mf < 4; mf++) {
        int row0 = m0 + mw + mf * 16 + g;
        #pragma unroll
        for (int nf = 0; nf < 4; nf++) {
            int col = n0 + nw + nf * 8 + 2 * tig;
            float b0 = bias[col], b1 = bias[col + 1];
            float v0 = c[mf][nf][0] + b0, v1 = c[mf][nf][1] + b1;
            float v2 = c[mf][nf][2] + b0, v3 = c[mf][nf][3] + b1;
            if (SILU) {
                v0 = rna_tf32(v0 / (1.0f + __expf(-v0)));
                v1 = rna_tf32(v1 / (1.0f + __expf(-v1)));
                v2 = rna_tf32(v2 / (1.0f + __expf(-v2)));
                v3 = rna_tf32(v3 / (1.0f + __expf(-v3)));
            }
            if (row0 < M)
                *(float2*)(Cm + (size_t)(outbase + row0) * Nd + col) = make_float2(v0, v1);
            if (row0 + 8 < M)
                *(float2*)(Cm + (size_t)(outbase + row0 + 8) * Nd + col) = make_float2(v2, v3);
        }
    }
}

// ---------------- combine ----------------------------------------------------
__global__ void combine_k(const float* __restrict__ y, float* __restrict__ out) {
    int n = blockIdx.x;
    int r0 = g_row_of[n * 2], r1 = g_row_of[n * 2 + 1];
    float w0 = g_tok_w[n * 2], w1 = g_tok_w[n * 2 + 1];
    const float* y0 = y + (size_t)r0 * CDIM;
    const float* y1 = y + (size_t)r1 * CDIM;
    float* o = out + (size_t)n * CDIM;
    for (int c = threadIdx.x; c < CDIM; c += blockDim.x)
        o[c] += w0 * y0[c] + w1 * y1[c];
}

// ---------------- launch -----------------------------------------------------
extern "C" void kernel_launch(void* const* d_in, const int* in_sizes, int n_in,
                              void* d_out, int out_size) {
    const float* x   = (const float*)d_in[0];
    const float* rw1 = (const float*)d_in[1];
    const float* rb1 = (const float*)d_in[2];
    const float* rw2 = (const float*)d_in[3];
    const float* rb2 = (const float*)d_in[4];
    const float* ew1 = (const float*)d_in[5];
    const float* eb1 = (const float*)d_in[6];
    const float* ew2 = (const float*)d_in[7];
    const float* eb2 = (const float*)d_in[8];
    const float* sw1 = (const float*)d_in[9];
    const float* sb1 = (const float*)d_in[10];
    const float* sw2 = (const float*)d_in[11];
    const float* sb2 = (const float*)d_in[12];
    float* out = (float*)d_out;

    float *hbuf, *ybuf, *hsbuf, *xr, *ew1r, *ew2r, *sw1r, *sw2r;
    cudaGetSymbolAddress((void**)&hbuf,  g_hbuf);
    cudaGetSymbolAddress((void**)&ybuf,  g_ybuf);
    cudaGetSymbolAddress((void**)&hsbuf, g_hs);
    cudaGetSymbolAddress((void**)&xr,    g_xr);
    cudaGetSymbolAddress((void**)&ew1r,  g_ew1r);
    cudaGetSymbolAddress((void**)&ew2r,  g_ew2r);
    cudaGetSymbolAddress((void**)&sw1r,  g_sw1r);
    cudaGetSymbolAddress((void**)&sw2r,  g_sw2r);

    cudaFuncSetAttribute(tgemm_k<false, false, true>,
                         cudaFuncAttributeMaxDynamicSharedMemorySize, SMEM_BYTES);
    cudaFuncSetAttribute(tgemm_k<false, false, false>,
                         cudaFuncAttributeMaxDynamicSharedMemorySize, SMEM_BYTES);
    cudaFuncSetAttribute(tgemm_k<true, true, true>,
                         cudaFuncAttributeMaxDynamicSharedMemorySize, SMEM_BYTES);
    cudaFuncSetAttribute(tgemm_k<true, false, false>,
                         cudaFuncAttributeMaxDynamicSharedMemorySize, SMEM_BYTES);

    init_k<<<1, 32>>>();
    router_k<<<NTOK, 256>>>(x, rw1, rb1, rw2, rb2);
    scan_k<<<1, 32>>>();
    fill_k<<<(NTOK + 255) / 256, 256>>>();

    // tf32 rounding pre-pass (RN, unbiased)
    {
        auto rnd = [&](const float* in, float* o, size_t n) {
            int n4 = (int)(n / 4);
            round_k<<<(n4 + 255) / 256, 256>>>((const float4*)in, (float4*)o, n4);
        };
        rnd(x,   xr,   (size_t)NTOK * CDIM);
        rnd(ew1, ew1r, (size_t)NEXP * CDIM * IDIM);
        rnd(ew2, ew2r, (size_t)NEXP * IDIM * CDIM);
        rnd(sw1, sw1r, (size_t)CDIM * IDIM);
        rnd(sw2, sw2r, (size_t)IDIM * CDIM);
    }

    // shared expert
    tgemm_k<false, false, true><<<dim3(IDIM / BN, NTOK / BM), THREADS, SMEM_BYTES>>>(
        xr, sw1r, sb1, hsbuf, NTOK, CDIM, IDIM);
    tgemm_k<false, false, false><<<dim3(CDIM / BN, NTOK / BM), THREADS, SMEM_BYTES>>>(
        hsbuf, sw2r, sb2, out, NTOK, IDIM, CDIM);

    // routed experts
    tgemm_k<true, true, true><<<dim3(IDIM / BN, NTOK / BM, NEXP), THREADS, SMEM_BYTES>>>(
        xr, ew1r, eb1, hbuf, 0, CDIM, IDIM);
    tgemm_k<true, false, false><<<dim3(CDIM / BN, NTOK / BM, NEXP), THREADS, SMEM_BYTES>>>(
        hbuf, ew2r, eb2, ybuf, 0, IDIM, CDIM);

    combine_k<<<NTOK, 256>>>(ybuf, out);
}

// round 4
// speedup vs baseline: 3.2445x; 1.0779x over previous
#include <cuda_runtime.h>
#include <math.h>
#include <stdint.h>

#define NTOK 2048
#define CDIM 1024
#define IDIM 4096
#define NEXP 8
#define HR   256

#define BM 128
#define BN 128
#define BK 32
#define THREADS 128   // 4 warps, 64x64 warp tiles

// smem: 3-stage; A 128x36 floats, B 32x132 floats per stage
#define A_ST 36
#define B_ST 132
#define ABUF 4608          // floats per A stage
#define BBUF 4224          // floats per B stage
#define B_BASE (3 * ABUF)  // 13824
#define SMEM_FLOATS (3 * (ABUF + BBUF))
#define SMEM_BYTES (SMEM_FLOATS * 4)   // 105984

// ---------------- scratch ----------------------------------------------------
__device__ int   g_count[NEXP];
__device__ int   g_cursor[NEXP];
__device__ int   g_base[NEXP];
__device__ int   g_row_tok[NTOK * 2];
__device__ int   g_row_of[NTOK * 2];
__device__ int   g_tok_eidx[NTOK * 2];
__device__ float g_tok_w[NTOK * 2];
__device__ float g_hbuf[(size_t)NTOK * 2 * IDIM];   // expert hidden
__device__ float g_ybuf[(size_t)NTOK * 2 * CDIM];   // expert out rows
__device__ float g_hs[(size_t)NTOK * IDIM];         // shared hidden

// ---------------- helpers ----------------------------------------------------
__device__ __forceinline__ uint32_t smem_u32(const void* p) {
    uint32_t a;
    asm("{ .reg .u64 t; cvta.to.shared.u64 t, %1; cvt.u32.u64 %0, t; }" : "=r"(a) : "l"(p));
    return a;
}
__device__ __forceinline__ uint32_t rna_u(float f) {
    uint32_t u;
    asm("cvt.rna.tf32.f32 %0, %1;" : "=r"(u) : "f"(f));
    return u;
}
__device__ __forceinline__ void cp16(uint32_t dst, const float* src) {
    asm volatile("cp.async.cg.shared.global [%0], [%1], 16;" :: "r"(dst), "l"(src) : "memory");
}
__device__ __forceinline__ void cp_commit() {
    asm volatile("cp.async.commit_group;" ::: "memory");
}
template<int N> __device__ __forceinline__ void cp_wait() {
    asm volatile("cp.async.wait_group %0;" :: "n"(N) : "memory");
}
__device__ __forceinline__ void mma8(float* c, const uint32_t* a, const uint32_t* b) {
    asm volatile(
        "mma.sync.aligned.m16n8k8.row.col.f32.tf32.tf32.f32 "
        "{%0,%1,%2,%3}, {%4,%5,%6,%7}, {%8,%9}, {%0,%1,%2,%3};"
        : "+f"(c[0]), "+f"(c[1]), "+f"(c[2]), "+f"(c[3])
        : "r"(a[0]), "r"(a[1]), "r"(a[2]), "r"(a[3]), "r"(b[0]), "r"(b[1]));
}

// ---------------- init -------------------------------------------------------
__global__ void init_k() {
    int t = threadIdx.x;
    if (t < NEXP) { g_count[t] = 0; g_cursor[t] = 0; }
}

// ---------------- router: 8 tokens per block, exact fp32 ---------------------
__global__ void router_k(const float* __restrict__ x,
                         const float* __restrict__ rw1, const float* __restrict__ rb1,
                         const float* __restrict__ rw2, const float* __restrict__ rb2) {
    __shared__ float xs[8][CDIM];
    __shared__ float hs[8][HR];
    int t = threadIdx.x;
    int tok0 = blockIdx.x * 8;
    // load 8 token rows (8192 floats = 2048 float4)
    {
        const float4* xr = (const float4*)(x + (size_t)tok0 * CDIM);
        float4* xd = (float4*)&xs[0][0];
        for (int i = t; i < 8 * CDIM / 4; i += 256) xd[i] = xr[i];
    }
    __syncthreads();
    // hidden unit t for all 8 tokens
    float acc[8];
    float b = rb1[t];
    #pragma unroll
    for (int k = 0; k < 8; k++) acc[k] = b;
    #pragma unroll 4
    for (int c = 0; c < CDIM; c++) {
        float w = rw1[(size_t)c * HR + t];
        #pragma unroll
        for (int k = 0; k < 8; k++) acc[k] += xs[k][c] * w;
    }
    #pragma unroll
    for (int k = 0; k < 8; k++) hs[k][t] = fmaxf(acc[k], 0.0f);
    __syncthreads();
    // warp w handles token w; lanes 0..7 compute logits
    int w = t >> 5, l = t & 31;
    float lg = 0.0f;
    if (l < NEXP) {
        lg = rb2[l];
        for (int h = 0; h < HR; h++) lg += hs[w][h] * rw2[(size_t)h * NEXP + l];
    }
    // lane 0 gathers and finishes
    float lgs[NEXP];
    #pragma unroll
    for (int e = 0; e < NEXP; e++) lgs[e] = __shfl_sync(0xffffffffu, lg, e);
    if (l == 0) {
        int n = tok0 + w;
        float mx = lgs[0];
        for (int e = 1; e < NEXP; e++) mx = fmaxf(mx, lgs[e]);
        float ge[NEXP]; float s = 0.0f;
        for (int e = 0; e < NEXP; e++) { ge[e] = expf(lgs[e] - mx); s += ge[e]; }
        for (int e = 0; e < NEXP; e++) ge[e] /= s;
        int i0 = 0;
        for (int e = 1; e < NEXP; e++) if (ge[e] > ge[i0]) i0 = e;
        int i1 = -1;
        for (int e = 0; e < NEXP; e++) {
            if (e == i0) continue;
            if (i1 < 0 || ge[e] > ge[i1]) i1 = e;
        }
        float a = expf(ge[i0] * 0.5f), c = expf(ge[i1] * 0.5f);
        float inv = 1.0f / (a + c);
        g_tok_eidx[n * 2] = i0;  g_tok_eidx[n * 2 + 1] = i1;
        g_tok_w[n * 2] = a * inv;
        g_tok_w[n * 2 + 1] = c * inv;
        atomicAdd(&g_count[i0], 1);
        atomicAdd(&g_count[i1], 1);
    }
}

__global__ void scan_k() {
    if (threadIdx.x == 0) {
        int s = 0;
        for (int e = 0; e < NEXP; e++) { g_base[e] = s; s += g_count[e]; }
    }
}

__global__ void fill_k() {
    int n = blockIdx.x * blockDim.x + threadIdx.x;
    if (n >= NTOK) return;
    #pragma unroll
    for (int k = 0; k < 2; k++) {
        int e = g_tok_eidx[n * 2 + k];
        int slot = atomicAdd(&g_cursor[e], 1);
        int row = g_base[e] + slot;
        g_row_tok[row] = n;
        g_row_of[n * 2 + k] = row;
    }
}

// ---------------- tf32 mma.sync GEMM, 4 warps, 64x64 warp tiles --------------
// C[M,Nd] = act(A[M,K] @ Bw[K,Nd] + bias); Bw row-major [K,Nd].
// tf32 rounding (RNA) applied in-register after LDS (idempotent).
template<bool EXPERT, bool GATHER, bool SILU>
__global__ void __launch_bounds__(THREADS, 2) tgemm_k(
    const float* __restrict__ A, const float* __restrict__ Bw,
    const float* __restrict__ bias, float* __restrict__ Cm,
    int M, int K, int Nd)
{
    extern __shared__ float sm[];
    int rowbase = 0;
    if (EXPERT) {
        int e = blockIdx.z;
        M = g_count[e];
        rowbase = g_base[e];
        Bw   += (size_t)e * K * Nd;
        bias += (size_t)e * Nd;
    }
    int m0 = blockIdx.y * BM;
    if (m0 >= M) return;
    int n0 = blockIdx.x * BN;
    int t = threadIdx.x;
    int wid = t >> 5, lane = t & 31;
    int g = lane >> 2, tig = lane & 3;
    int mw = (wid & 1) * 64, nw = (wid >> 1) * 64;
    uint32_t sbase = smem_u32(sm);

    // ---- load roles: A 1024 chunks (8/thread, +16 rows apart), B same ----
    int ar = t >> 3, aq = t & 3 | ((t & 4) ? 4 : 0); // aq = t & 7
    aq = t & 7;
    int arr = m0 + ar;
    int arc = arr < M ? arr : (M - 1);
    int asrc0 = GATHER ? g_row_tok[rowbase + arc] : (EXPERT ? (rowbase + arc) : arc);
    const float* aptr = A + (size_t)asrc0 * K + aq * 4;   // + i: row += 16
    const float* aptrs[8];
    uint32_t aoffs[8];
    #pragma unroll
    for (int i = 0; i < 8; i++) {
        int r = ar + 16 * i;
        int rr = m0 + r;
        int rc = rr < M ? rr : (M - 1);
        int src = GATHER ? g_row_tok[rowbase + rc] : (EXPERT ? (rowbase + rc) : rc);
        aptrs[i] = A + (size_t)src * K + aq * 4;
        aoffs[i] = (uint32_t)((r * A_ST + aq * 4) * 4);
    }
    int br = t >> 5, bq = t & 31;   // +i: row += 4
    const float* bptr = Bw + (size_t)br * Nd + n0 + bq * 4;
    uint32_t boff0 = (uint32_t)((br * B_ST + bq * 4) * 4);

    float c[4][8][4];
    #pragma unroll
    for (int mf = 0; mf < 4; mf++)
        #pragma unroll
        for (int nf = 0; nf < 8; nf++)
            #pragma unroll
            for (int i = 0; i < 4; i++) c[mf][nf][i] = 0.0f;

    int iters = K / BK;

    // prologue: stages 0 and 1
    #pragma unroll
    for (int s = 0; s < 2; s++) {
        uint32_t ab = sbase + s * (ABUF * 4);
        uint32_t bb = sbase + (B_BASE + s * BBUF) * 4;
        int kof = s * BK;
        #pragma unroll
        for (int i = 0; i < 8; i++) cp16(ab + aoffs[i], aptrs[i] + kof);
        #pragma unroll
        for (int i = 0; i < 8; i++)
            cp16(bb + boff0 + i * (4 * B_ST * 4), bptr + (size_t)(kof + 4 * i) * Nd);
        cp_commit();
    }

    for (int it = 0; it < iters; it++) {
        cp_wait<1>();
        __syncthreads();
        if (it + 2 < iters) {
            int s = (it + 2) % 3;
            uint32_t ab = sbase + s * (ABUF * 4);
            uint32_t bb = sbase + (B_BASE + s * BBUF) * 4;
            int kof = (it + 2) * BK;
            #pragma unroll
            for (int i = 0; i < 8; i++) cp16(ab + aoffs[i], aptrs[i] + kof);
            #pragma unroll
            for (int i = 0; i < 8; i++)
                cp16(bb + boff0 + i * (4 * B_ST * 4), bptr + (size_t)(kof + 4 * i) * Nd);
        }
        cp_commit();   // keep group count in lockstep even on tail iters

        const float* Ab = sm + (it % 3) * ABUF;
        const float* Bb = sm + B_BASE + (it % 3) * BBUF;
        #pragma unroll
        for (int ks = 0; ks < 4; ks++) {
            uint32_t a[4][4], b[8][2];
            #pragma unroll
            for (int mf = 0; mf < 4; mf++) {
                const float* ap = Ab + (mw + mf * 16 + g) * A_ST + ks * 8 + tig;
                a[mf][0] = rna_u(ap[0]);
                a[mf][1] = rna_u(ap[8 * A_ST]);
                a[mf][2] = rna_u(ap[4]);
                a[mf][3] = rna_u(ap[8 * A_ST + 4]);
            }
            #pragma unroll
            for (int nf = 0; nf < 8; nf++) {
                const float* bp = Bb + (ks * 8 + tig) * B_ST + nw + nf * 8 + g;
                b[nf][0] = rna_u(bp[0]);
                b[nf][1] = rna_u(bp[4 * B_ST]);
            }
            #pragma unroll
            for (int mf = 0; mf < 4; mf++)
                #pragma unroll
                for (int nf = 0; nf < 8; nf++)
                    mma8(c[mf][nf], a[mf], b[nf]);
        }
        __syncthreads();
    }

    // ---- epilogue ----
    int outbase = EXPERT ? rowbase : 0;
    float2 bv[8];
    #pragma unroll
    for (int nf = 0; nf < 8; nf++)
        bv[nf] = *(const float2*)(bias + n0 + nw + nf * 8 + 2 * tig);
    #pragma unroll
    for (int mf = 0; mf < 4; mf++) {
        int row0 = m0 + mw + mf * 16 + g;
        #pragma unroll
        for (int nf = 0; nf < 8; nf++) {
            int col = n0 + nw + nf * 8 + 2 * tig;
            float v0 = c[mf][nf][0] + bv[nf].x, v1 = c[mf][nf][1] + bv[nf].y;
            float v2 = c[mf][nf][2] + bv[nf].x, v3 = c[mf][nf][3] + bv[nf].y;
            if (SILU) {
                v0 = v0 / (1.0f + __expf(-v0));
                v1 = v1 / (1.0f + __expf(-v1));
                v2 = v2 / (1.0f + __expf(-v2));
                v3 = v3 / (1.0f + __expf(-v3));
            }
            if (row0 < M)
                *(float2*)(Cm + (size_t)(outbase + row0) * Nd + col) = make_float2(v0, v1);
            if (row0 + 8 < M)
                *(float2*)(Cm + (size_t)(outbase + row0 + 8) * Nd + col) = make_float2(v2, v3);
        }
    }
}

// ---------------- combine ----------------------------------------------------
__global__ void combine_k(const float* __restrict__ y, float* __restrict__ out) {
    int n = blockIdx.x;
    int r0 = g_row_of[n * 2], r1 = g_row_of[n * 2 + 1];
    float w0 = g_tok_w[n * 2], w1 = g_tok_w[n * 2 + 1];
    const float4* y0 = (const float4*)(y + (size_t)r0 * CDIM);
    const float4* y1 = (const float4*)(y + (size_t)r1 * CDIM);
    float4* o = (float4*)(out + (size_t)n * CDIM);
    for (int c = threadIdx.x; c < CDIM / 4; c += blockDim.x) {
        float4 a = y0[c], b = y1[c], v = o[c];
        v.x += w0 * a.x + w1 * b.x;
        v.y += w0 * a.y + w1 * b.y;
        v.z += w0 * a.z + w1 * b.z;
        v.w += w0 * a.w + w1 * b.w;
        o[c] = v;
    }
}

// ---------------- launch -----------------------------------------------------
extern "C" void kernel_launch(void* const* d_in, const int* in_sizes, int n_in,
                              void* d_out, int out_size) {
    const float* x   = (const float*)d_in[0];
    const float* rw1 = (const float*)d_in[1];
    const float* rb1 = (const float*)d_in[2];
    const float* rw2 = (const float*)d_in[3];
    const float* rb2 = (const float*)d_in[4];
    const float* ew1 = (const float*)d_in[5];
    const float* eb1 = (const float*)d_in[6];
    const float* ew2 = (const float*)d_in[7];
    const float* eb2 = (const float*)d_in[8];
    const float* sw1 = (const float*)d_in[9];
    const float* sb1 = (const float*)d_in[10];
    const float* sw2 = (const float*)d_in[11];
    const float* sb2 = (const float*)d_in[12];
    float* out = (float*)d_out;

    float *hbuf, *ybuf, *hsbuf;
    cudaGetSymbolAddress((void**)&hbuf,  g_hbuf);
    cudaGetSymbolAddress((void**)&ybuf,  g_ybuf);
    cudaGetSymbolAddress((void**)&hsbuf, g_hs);

    cudaFuncSetAttribute(tgemm_k<false, false, true>,
                         cudaFuncAttributeMaxDynamicSharedMemorySize, SMEM_BYTES);
    cudaFuncSetAttribute(tgemm_k<false, false, false>,
                         cudaFuncAttributeMaxDynamicSharedMemorySize, SMEM_BYTES);
    cudaFuncSetAttribute(tgemm_k<true, true, true>,
                         cudaFuncAttributeMaxDynamicSharedMemorySize, SMEM_BYTES);
    cudaFuncSetAttribute(tgemm_k<true, false, false>,
                         cudaFuncAttributeMaxDynamicSharedMemorySize, SMEM_BYTES);

    init_k<<<1, 32>>>();
    router_k<<<NTOK / 8, 256>>>(x, rw1, rb1, rw2, rb2);
    scan_k<<<1, 32>>>();
    fill_k<<<(NTOK + 255) / 256, 256>>>();

    // routed experts first (heavy kernels land at ncu capture slots)
    tgemm_k<true, true, true><<<dim3(IDIM / BN, NTOK / BM, NEXP), THREADS, SMEM_BYTES>>>(
        x, ew1, eb1, hbuf, 0, CDIM, IDIM);
    tgemm_k<true, false, false><<<dim3(CDIM / BN, NTOK / BM, NEXP), THREADS, SMEM_BYTES>>>(
        hbuf, ew2, eb2, ybuf, 0, IDIM, CDIM);

    // shared expert
    tgemm_k<false, false, true><<<dim3(IDIM / BN, NTOK / BM), THREADS, SMEM_BYTES>>>(
        x, sw1, sb1, hsbuf, NTOK, CDIM, IDIM);
    tgemm_k<false, false, false><<<dim3(CDIM / BN, NTOK / BM), THREADS, SMEM_BYTES>>>(
        hsbuf, sw2, sb2, out, NTOK, IDIM, CDIM);

    combine_k<<<NTOK, 256>>>(ybuf, out);
}

// round 5
// speedup vs baseline: 3.5603x; 1.0974x over previous
#include <cuda_runtime.h>
#include <math.h>
#include <stdint.h>

#define NTOK 2048
#define CDIM 1024
#define IDIM 4096
#define NEXP 8
#define HR   256

#define BM 128
#define BN 128
#define BK 32
#define THREADS 128   // 4 warps, 64x64 warp tiles

// smem: 3-stage; A 128x36 floats, B 32x136 floats per stage
#define A_ST 36
#define B_ST 136
#define ABUF 4608               // floats per A stage
#define BBUF 4352               // floats per B stage
#define B_BASE (3 * ABUF)
#define SMEM_FLOATS (3 * (ABUF + BBUF))
#define SMEM_BYTES (SMEM_FLOATS * 4)   // 107520

// ---------------- scratch ----------------------------------------------------
__device__ int   g_count[NEXP];
__device__ int   g_cursor[NEXP];
__device__ int   g_base[NEXP];
__device__ int   g_row_tok[NTOK * 2];
__device__ int   g_row_of[NTOK * 2];
__device__ int   g_tok_eidx[NTOK * 2];
__device__ float g_tok_w[NTOK * 2];
__device__ float g_xr[(size_t)NTOK * CDIM];         // tf32-rounded x
__device__ float g_hbuf[(size_t)NTOK * 2 * IDIM];   // expert hidden (tf32-rounded)
__device__ float g_ybuf[(size_t)NTOK * 2 * CDIM];   // expert out rows
__device__ float g_hs[(size_t)NTOK * IDIM];         // shared hidden (tf32-rounded)

// ---------------- helpers ----------------------------------------------------
__device__ __forceinline__ uint32_t smem_u32(const void* p) {
    uint32_t a;
    asm("{ .reg .u64 t; cvta.to.shared.u64 t, %1; cvt.u32.u64 %0, t; }" : "=r"(a) : "l"(p));
    return a;
}
__device__ __forceinline__ uint32_t rna_u(float f) {
    uint32_t u;
    asm("cvt.rna.tf32.f32 %0, %1;" : "=r"(u) : "f"(f));
    return u;
}
__device__ __forceinline__ float rna_f(float f) { return __uint_as_float(rna_u(f)); }
__device__ __forceinline__ void cp16(uint32_t dst, const float* src) {
    asm volatile("cp.async.cg.shared.global [%0], [%1], 16;" :: "r"(dst), "l"(src) : "memory");
}
__device__ __forceinline__ void cp_commit() {
    asm volatile("cp.async.commit_group;" ::: "memory");
}
template<int N> __device__ __forceinline__ void cp_wait() {
    asm volatile("cp.async.wait_group %0;" :: "n"(N) : "memory");
}
__device__ __forceinline__ void mma8(float* c, const uint32_t* a, const uint32_t* b) {
    asm volatile(
        "mma.sync.aligned.m16n8k8.row.col.f32.tf32.tf32.f32 "
        "{%0,%1,%2,%3}, {%4,%5,%6,%7}, {%8,%9}, {%0,%1,%2,%3};"
        : "+f"(c[0]), "+f"(c[1]), "+f"(c[2]), "+f"(c[3])
        : "r"(a[0]), "r"(a[1]), "r"(a[2]), "r"(a[3]), "r"(b[0]), "r"(b[1]));
}
__device__ __forceinline__ void ldsm4(uint32_t* r, uint32_t addr) {
    asm volatile("ldmatrix.sync.aligned.m8n8.x4.shared.b16 {%0,%1,%2,%3}, [%4];"
        : "=r"(r[0]), "=r"(r[1]), "=r"(r[2]), "=r"(r[3]) : "r"(addr));
}

// ---------------- init -------------------------------------------------------
__global__ void init_k() {
    int t = threadIdx.x;
    if (t < NEXP) { g_count[t] = 0; g_cursor[t] = 0; }
}

// ---------------- router: 8 tokens per block, exact fp32 ---------------------
__global__ void router_k(const float* __restrict__ x,
                         const float* __restrict__ rw1, const float* __restrict__ rb1,
                         const float* __restrict__ rw2, const float* __restrict__ rb2) {
    __shared__ float xs[8][CDIM];
    __shared__ float hs[8][HR];
    int t = threadIdx.x;
    int tok0 = blockIdx.x * 8;
    {
        const float4* xr = (const float4*)(x + (size_t)tok0 * CDIM);
        float4* xd = (float4*)&xs[0][0];
        for (int i = t; i < 8 * CDIM / 4; i += 256) xd[i] = xr[i];
    }
    __syncthreads();
    float acc[8];
    float b = rb1[t];
    #pragma unroll
    for (int k = 0; k < 8; k++) acc[k] = b;
    #pragma unroll 4
    for (int c = 0; c < CDIM; c++) {
        float w = rw1[(size_t)c * HR + t];
        #pragma unroll
        for (int k = 0; k < 8; k++) acc[k] += xs[k][c] * w;
    }
    #pragma unroll
    for (int k = 0; k < 8; k++) hs[k][t] = fmaxf(acc[k], 0.0f);
    __syncthreads();
    int w = t >> 5, l = t & 31;
    float lg = 0.0f;
    if (l < NEXP) {
        lg = rb2[l];
        for (int h = 0; h < HR; h++) lg += hs[w][h] * rw2[(size_t)h * NEXP + l];
    }
    float lgs[NEXP];
    #pragma unroll
    for (int e = 0; e < NEXP; e++) lgs[e] = __shfl_sync(0xffffffffu, lg, e);
    if (l == 0) {
        int n = tok0 + w;
        float mx = lgs[0];
        for (int e = 1; e < NEXP; e++) mx = fmaxf(mx, lgs[e]);
        float ge[NEXP]; float s = 0.0f;
        for (int e = 0; e < NEXP; e++) { ge[e] = expf(lgs[e] - mx); s += ge[e]; }
        for (int e = 0; e < NEXP; e++) ge[e] /= s;
        int i0 = 0;
        for (int e = 1; e < NEXP; e++) if (ge[e] > ge[i0]) i0 = e;
        int i1 = -1;
        for (int e = 0; e < NEXP; e++) {
            if (e == i0) continue;
            if (i1 < 0 || ge[e] > ge[i1]) i1 = e;
        }
        float a = expf(ge[i0] * 0.5f), c = expf(ge[i1] * 0.5f);
        float inv = 1.0f / (a + c);
        g_tok_eidx[n * 2] = i0;  g_tok_eidx[n * 2 + 1] = i1;
        g_tok_w[n * 2] = a * inv;
        g_tok_w[n * 2 + 1] = c * inv;
        atomicAdd(&g_count[i0], 1);
        atomicAdd(&g_count[i1], 1);
    }
}

__global__ void scan_k() {
    if (threadIdx.x == 0) {
        int s = 0;
        for (int e = 0; e < NEXP; e++) { g_base[e] = s; s += g_count[e]; }
    }
}

__global__ void fill_k() {
    int n = blockIdx.x * blockDim.x + threadIdx.x;
    if (n >= NTOK) return;
    #pragma unroll
    for (int k = 0; k < 2; k++) {
        int e = g_tok_eidx[n * 2 + k];
        int slot = atomicAdd(&g_cursor[e], 1);
        int row = g_base[e] + slot;
        g_row_tok[row] = n;
        g_row_of[n * 2 + k] = row;
    }
}

// ---------------- tf32 rounding pass (x only) --------------------------------
__global__ void round_k(const float4* __restrict__ in, float4* __restrict__ out, int n4) {
    int i = blockIdx.x * blockDim.x + threadIdx.x;
    if (i >= n4) return;
    float4 v = in[i];
    v.x = rna_f(v.x); v.y = rna_f(v.y);
    v.z = rna_f(v.z); v.w = rna_f(v.w);
    out[i] = v;
}

// ---------------- tf32 mma.sync GEMM, 4 warps, 64x64 warp tiles --------------
// C[M,Nd] = act(A[M,K] @ Bw[K,Nd] + bias); Bw row-major [K,Nd].
// A must be pre-rounded to tf32 (ldmatrix path, no cvt). B cvt'd in-register.
template<bool EXPERT, bool GATHER, bool SILU>
__global__ void __launch_bounds__(THREADS, 2) tgemm_k(
    const float* __restrict__ A, const float* __restrict__ Bw,
    const float* __restrict__ bias, float* __restrict__ Cm,
    int M, int K, int Nd)
{
    extern __shared__ float sm[];
    int rowbase = 0;
    if (EXPERT) {
        int e = blockIdx.z;
        M = g_count[e];
        rowbase = g_base[e];
        Bw   += (size_t)e * K * Nd;
        bias += (size_t)e * Nd;
    }
    int m0 = blockIdx.y * BM;
    if (m0 >= M) return;
    int n0 = blockIdx.x * BN;
    int t = threadIdx.x;
    int wid = t >> 5, lane = t & 31;
    int g = lane >> 2, tig = lane & 3;
    int mw = (wid & 1) * 64, nw = (wid >> 1) * 64;
    uint32_t sbase = smem_u32(sm);

    // ---- A cp.async roles: 8 chunks/thread, rows 16 apart ----
    int ar = t >> 3, aq = t & 7;
    const float* aptrs[8];
    uint32_t aoffs[8];
    #pragma unroll
    for (int i = 0; i < 8; i++) {
        int r = ar + 16 * i;
        int rr = m0 + r;
        int rc = rr < M ? rr : (M - 1);
        int src = GATHER ? g_row_tok[rowbase + rc] : (EXPERT ? (rowbase + rc) : rc);
        aptrs[i] = A + (size_t)src * K + aq * 4;
        aoffs[i] = (uint32_t)((r * A_ST + aq * 4) * 4);
    }
    // ---- B cp.async roles ----
    int br = t >> 5, bq = t & 31;   // +i: row += 4
    const float* bptr = Bw + (size_t)br * Nd + n0 + bq * 4;
    uint32_t boff0 = (uint32_t)((br * B_ST + bq * 4) * 4);

    // ---- ldmatrix lane address (A fragments) ----
    // matrix idx = lane>>3: bit0 -> +8 rows, bit1 -> +4 k-floats (16B)
    uint32_t laneA = (uint32_t)(((mw + (lane & 7) + ((lane >> 3) & 1) * 8) * A_ST
                                 + ((lane >> 4) & 1) * 4) * 4);

    float c[4][8][4];
    #pragma unroll
    for (int mf = 0; mf < 4; mf++)
        #pragma unroll
        for (int nf = 0; nf < 8; nf++)
            #pragma unroll
            for (int i = 0; i < 4; i++) c[mf][nf][i] = 0.0f;

    int iters = K / BK;

    #pragma unroll
    for (int s = 0; s < 2; s++) {
        uint32_t ab = sbase + s * (ABUF * 4);
        uint32_t bb = sbase + (B_BASE + s * BBUF) * 4;
        int kof = s * BK;
        #pragma unroll
        for (int i = 0; i < 8; i++) cp16(ab + aoffs[i], aptrs[i] + kof);
        #pragma unroll
        for (int i = 0; i < 8; i++)
            cp16(bb + boff0 + i * (4 * B_ST * 4), bptr + (size_t)(kof + 4 * i) * Nd);
        cp_commit();
    }

    for (int it = 0; it < iters; it++) {
        cp_wait<1>();
        __syncthreads();
        if (it + 2 < iters) {
            int s = (it + 2) % 3;
            uint32_t ab = sbase + s * (ABUF * 4);
            uint32_t bb = sbase + (B_BASE + s * BBUF) * 4;
            int kof = (it + 2) * BK;
            #pragma unroll
            for (int i = 0; i < 8; i++) cp16(ab + aoffs[i], aptrs[i] + kof);
            #pragma unroll
            for (int i = 0; i < 8; i++)
                cp16(bb + boff0 + i * (4 * B_ST * 4), bptr + (size_t)(kof + 4 * i) * Nd);
        }
        cp_commit();

        uint32_t Ab = sbase + (it % 3) * (ABUF * 4);
        const float* Bb = sm + B_BASE + (it % 3) * BBUF;
        #pragma unroll
        for (int ks = 0; ks < 4; ks++) {
            uint32_t a[4][4], b[8][2];
            #pragma unroll
            for (int mf = 0; mf < 4; mf++)
                ldsm4(a[mf], Ab + laneA + (uint32_t)(mf * 16 * A_ST * 4 + ks * 32));
            #pragma unroll
            for (int nf = 0; nf < 8; nf++) {
                const float* bp = Bb + (ks * 8 + tig) * B_ST + nw + nf * 8 + g;
                b[nf][0] = rna_u(bp[0]);
                b[nf][1] = rna_u(bp[4 * B_ST]);
            }
            #pragma unroll
            for (int mf = 0; mf < 4; mf++)
                #pragma unroll
                for (int nf = 0; nf < 8; nf++)
                    mma8(c[mf][nf], a[mf], b[nf]);
        }
        __syncthreads();
    }

    // ---- epilogue ----
    int outbase = EXPERT ? rowbase : 0;
    float2 bv[8];
    #pragma unroll
    for (int nf = 0; nf < 8; nf++)
        bv[nf] = *(const float2*)(bias + n0 + nw + nf * 8 + 2 * tig);
    #pragma unroll
    for (int mf = 0; mf < 4; mf++) {
        int row0 = m0 + mw + mf * 16 + g;
        #pragma unroll
        for (int nf = 0; nf < 8; nf++) {
            int col = n0 + nw + nf * 8 + 2 * tig;
            float v0 = c[mf][nf][0] + bv[nf].x, v1 = c[mf][nf][1] + bv[nf].y;
            float v2 = c[mf][nf][2] + bv[nf].x, v3 = c[mf][nf][3] + bv[nf].y;
            if (SILU) {   // round results so next GEMM's A-side is tf32-exact
                v0 = rna_f(v0 / (1.0f + __expf(-v0)));
                v1 = rna_f(v1 / (1.0f + __expf(-v1)));
                v2 = rna_f(v2 / (1.0f + __expf(-v2)));
                v3 = rna_f(v3 / (1.0f + __expf(-v3)));
            }
            if (row0 < M)
                *(float2*)(Cm + (size_t)(outbase + row0) * Nd + col) = make_float2(v0, v1);
            if (row0 + 8 < M)
                *(float2*)(Cm + (size_t)(outbase + row0 + 8) * Nd + col) = make_float2(v2, v3);
        }
    }
}

// ---------------- combine ----------------------------------------------------
__global__ void combine_k(const float* __restrict__ y, float* __restrict__ out) {
    int n = blockIdx.x;
    int r0 = g_row_of[n * 2], r1 = g_row_of[n * 2 + 1];
    float w0 = g_tok_w[n * 2], w1 = g_tok_w[n * 2 + 1];
    const float4* y0 = (const float4*)(y + (size_t)r0 * CDIM);
    const float4* y1 = (const float4*)(y + (size_t)r1 * CDIM);
    float4* o = (float4*)(out + (size_t)n * CDIM);
    for (int c = threadIdx.x; c < CDIM / 4; c += blockDim.x) {
        float4 a = y0[c], b = y1[c], v = o[c];
        v.x += w0 * a.x + w1 * b.x;
        v.y += w0 * a.y + w1 * b.y;
        v.z += w0 * a.z + w1 * b.z;
        v.w += w0 * a.w + w1 * b.w;
        o[c] = v;
    }
}

// ---------------- launch -----------------------------------------------------
extern "C" void kernel_launch(void* const* d_in, const int* in_sizes, int n_in,
                              void* d_out, int out_size) {
    const float* x   = (const float*)d_in[0];
    const float* rw1 = (const float*)d_in[1];
    const float* rb1 = (const float*)d_in[2];
    const float* rw2 = (const float*)d_in[3];
    const float* rb2 = (const float*)d_in[4];
    const float* ew1 = (const float*)d_in[5];
    const float* eb1 = (const float*)d_in[6];
    const float* ew2 = (const float*)d_in[7];
    const float* eb2 = (const float*)d_in[8];
    const float* sw1 = (const float*)d_in[9];
    const float* sb1 = (const float*)d_in[10];
    const float* sw2 = (const float*)d_in[11];
    const float* sb2 = (const float*)d_in[12];
    float* out = (float*)d_out;

    float *hbuf, *ybuf, *hsbuf, *xr;
    cudaGetSymbolAddress((void**)&hbuf,  g_hbuf);
    cudaGetSymbolAddress((void**)&ybuf,  g_ybuf);
    cudaGetSymbolAddress((void**)&hsbuf, g_hs);
    cudaGetSymbolAddress((void**)&xr,    g_xr);

    cudaFuncSetAttribute(tgemm_k<false, false, true>,
                         cudaFuncAttributeMaxDynamicSharedMemorySize, SMEM_BYTES);
    cudaFuncSetAttribute(tgemm_k<false, false, false>,
                         cudaFuncAttributeMaxDynamicSharedMemorySize, SMEM_BYTES);
    cudaFuncSetAttribute(tgemm_k<true, true, true>,
                         cudaFuncAttributeMaxDynamicSharedMemorySize, SMEM_BYTES);
    cudaFuncSetAttribute(tgemm_k<true, false, false>,
                         cudaFuncAttributeMaxDynamicSharedMemorySize, SMEM_BYTES);

    init_k<<<1, 32>>>();
    router_k<<<NTOK / 8, 256>>>(x, rw1, rb1, rw2, rb2);
    scan_k<<<1, 32>>>();
    fill_k<<<(NTOK + 255) / 256, 256>>>();
    round_k<<<(NTOK * CDIM / 4 + 255) / 256, 256>>>((const float4*)x, (float4*)xr,
                                                    NTOK * CDIM / 4);

    // routed experts
    tgemm_k<true, true, true><<<dim3(IDIM / BN, NTOK / BM, NEXP), THREADS, SMEM_BYTES>>>(
        xr, ew1, eb1, hbuf, 0, CDIM, IDIM);
    tgemm_k<true, false, false><<<dim3(CDIM / BN, NTOK / BM, NEXP), THREADS, SMEM_BYTES>>>(
        hbuf, ew2, eb2, ybuf, 0, IDIM, CDIM);

    // shared expert
    tgemm_k<false, false, true><<<dim3(IDIM / BN, NTOK / BM), THREADS, SMEM_BYTES>>>(
        xr, sw1, sb1, hsbuf, NTOK, CDIM, IDIM);
    tgemm_k<false, false, false><<<dim3(CDIM / BN, NTOK / BM), THREADS, SMEM_BYTES>>>(
        hsbuf, sw2, sb2, out, NTOK, IDIM, CDIM);

    combine_k<<<NTOK, 256>>>(ybuf, out);
}

// round 6
// speedup vs baseline: 5.2946x; 1.4871x over previous
#include <cuda_runtime.h>
#include <cuda_fp16.h>
#include <math.h>
#include <stdint.h>

#define NTOK 2048
#define CDIM 1024
#define IDIM 4096
#define NEXP 8
#define HR   256

#define BM 128
#define BN 128
#define BK 32
#define THREADS 128   // 4 warps, 64x64 warp tiles

// smem (half units): A stage 128x40, B stage 32x136, 3 stages
#define A_ST 40
#define B_ST 136
#define ABUF 5120               // halves per A stage
#define BBUF 4352               // halves per B stage
#define B_BASE (3 * ABUF)       // 15360
#define SMEM_BYTES ((3 * (ABUF + BBUF)) * 2)   // 56832

// ---------------- scratch ----------------------------------------------------
__device__ int    g_count[NEXP];
__device__ int    g_cursor[NEXP];
__device__ int    g_base[NEXP];
__device__ int    g_row_tok[NTOK * 2];
__device__ int    g_row_of[NTOK * 2];
__device__ int    g_tok_eidx[NTOK * 2];
__device__ float  g_tok_w[NTOK * 2];
__device__ __half g_xh[(size_t)NTOK * CDIM];            // fp16 x
__device__ __half g_ew1h[(size_t)NEXP * CDIM * IDIM];   // fp16 ew1
__device__ __half g_ew2h[(size_t)NEXP * IDIM * CDIM];   // fp16 ew2
__device__ __half g_sw1h[(size_t)CDIM * IDIM];          // fp16 sw1
__device__ __half g_sw2h[(size_t)IDIM * CDIM];          // fp16 sw2
__device__ __half g_hbufh[(size_t)NTOK * 2 * IDIM];     // expert hidden (fp16)
__device__ __half g_hsh[(size_t)NTOK * IDIM];           // shared hidden (fp16)
__device__ float  g_ybuf[(size_t)NTOK * 2 * CDIM];      // expert out rows (fp32)

// ---------------- helpers ----------------------------------------------------
__device__ __forceinline__ uint32_t smem_u32(const void* p) {
    uint32_t a;
    asm("{ .reg .u64 t; cvta.to.shared.u64 t, %1; cvt.u32.u64 %0, t; }" : "=r"(a) : "l"(p));
    return a;
}
__device__ __forceinline__ void cp16(uint32_t dst, const void* src) {
    asm volatile("cp.async.cg.shared.global [%0], [%1], 16;" :: "r"(dst), "l"(src) : "memory");
}
__device__ __forceinline__ void cp_commit() {
    asm volatile("cp.async.commit_group;" ::: "memory");
}
template<int N> __device__ __forceinline__ void cp_wait() {
    asm volatile("cp.async.wait_group %0;" :: "n"(N) : "memory");
}
__device__ __forceinline__ void mma16(float* c, const uint32_t* a, const uint32_t* b) {
    asm volatile(
        "mma.sync.aligned.m16n8k16.row.col.f32.f16.f16.f32 "
        "{%0,%1,%2,%3}, {%4,%5,%6,%7}, {%8,%9}, {%0,%1,%2,%3};"
        : "+f"(c[0]), "+f"(c[1]), "+f"(c[2]), "+f"(c[3])
        : "r"(a[0]), "r"(a[1]), "r"(a[2]), "r"(a[3]), "r"(b[0]), "r"(b[1]));
}
__device__ __forceinline__ void ldsm4(uint32_t* r, uint32_t addr) {
    asm volatile("ldmatrix.sync.aligned.m8n8.x4.shared.b16 {%0,%1,%2,%3}, [%4];"
        : "=r"(r[0]), "=r"(r[1]), "=r"(r[2]), "=r"(r[3]) : "r"(addr));
}
__device__ __forceinline__ void ldsm4t(uint32_t* r, uint32_t addr) {
    asm volatile("ldmatrix.sync.aligned.m8n8.x4.trans.shared.b16 {%0,%1,%2,%3}, [%4];"
        : "=r"(r[0]), "=r"(r[1]), "=r"(r[2]), "=r"(r[3]) : "r"(addr));
}
__device__ __forceinline__ uint32_t pkh2(float a, float b) {
    __half2 h = __floats2half2_rn(a, b);
    return *(uint32_t*)&h;
}

// ---------------- init -------------------------------------------------------
__global__ void init_k() {
    int t = threadIdx.x;
    if (t < NEXP) { g_count[t] = 0; g_cursor[t] = 0; }
}

// ---------------- router: 8 tokens per block, exact fp32 ---------------------
__global__ void router_k(const float* __restrict__ x,
                         const float* __restrict__ rw1, const float* __restrict__ rb1,
                         const float* __restrict__ rw2, const float* __restrict__ rb2) {
    __shared__ float xs[8][CDIM];
    __shared__ float hs[8][HR];
    int t = threadIdx.x;
    int tok0 = blockIdx.x * 8;
    {
        const float4* xr = (const float4*)(x + (size_t)tok0 * CDIM);
        float4* xd = (float4*)&xs[0][0];
        for (int i = t; i < 8 * CDIM / 4; i += 256) xd[i] = xr[i];
    }
    __syncthreads();
    float acc[8];
    float b = rb1[t];
    #pragma unroll
    for (int k = 0; k < 8; k++) acc[k] = b;
    #pragma unroll 4
    for (int c = 0; c < CDIM; c++) {
        float w = rw1[(size_t)c * HR + t];
        #pragma unroll
        for (int k = 0; k < 8; k++) acc[k] += xs[k][c] * w;
    }
    #pragma unroll
    for (int k = 0; k < 8; k++) hs[k][t] = fmaxf(acc[k], 0.0f);
    __syncthreads();
    int w = t >> 5, l = t & 31;
    float lg = 0.0f;
    if (l < NEXP) {
        lg = rb2[l];
        for (int h = 0; h < HR; h++) lg += hs[w][h] * rw2[(size_t)h * NEXP + l];
    }
    float lgs[NEXP];
    #pragma unroll
    for (int e = 0; e < NEXP; e++) lgs[e] = __shfl_sync(0xffffffffu, lg, e);
    if (l == 0) {
        int n = tok0 + w;
        float mx = lgs[0];
        for (int e = 1; e < NEXP; e++) mx = fmaxf(mx, lgs[e]);
        float ge[NEXP]; float s = 0.0f;
        for (int e = 0; e < NEXP; e++) { ge[e] = expf(lgs[e] - mx); s += ge[e]; }
        for (int e = 0; e < NEXP; e++) ge[e] /= s;
        int i0 = 0;
        for (int e = 1; e < NEXP; e++) if (ge[e] > ge[i0]) i0 = e;
        int i1 = -1;
        for (int e = 0; e < NEXP; e++) {
            if (e == i0) continue;
            if (i1 < 0 || ge[e] > ge[i1]) i1 = e;
        }
        float a = expf(ge[i0] * 0.5f), c = expf(ge[i1] * 0.5f);
        float inv = 1.0f / (a + c);
        g_tok_eidx[n * 2] = i0;  g_tok_eidx[n * 2 + 1] = i1;
        g_tok_w[n * 2] = a * inv;
        g_tok_w[n * 2 + 1] = c * inv;
        atomicAdd(&g_count[i0], 1);
        atomicAdd(&g_count[i1], 1);
    }
}

__global__ void scan_k() {
    if (threadIdx.x == 0) {
        int s = 0;
        for (int e = 0; e < NEXP; e++) { g_base[e] = s; s += g_count[e]; }
    }
}

__global__ void fill_k() {
    int n = blockIdx.x * blockDim.x + threadIdx.x;
    if (n >= NTOK) return;
    #pragma unroll
    for (int k = 0; k < 2; k++) {
        int e = g_tok_eidx[n * 2 + k];
        int slot = atomicAdd(&g_cursor[e], 1);
        int row = g_base[e] + slot;
        g_row_tok[row] = n;
        g_row_of[n * 2 + k] = row;
    }
}

// ---------------- fp32 -> fp16 conversion ------------------------------------
__global__ void f2h_k(const float4* __restrict__ in, uint4* __restrict__ out, int n8) {
    int i = blockIdx.x * blockDim.x + threadIdx.x;
    if (i >= n8) return;
    float4 v0 = in[2 * i], v1 = in[2 * i + 1];
    uint4 o;
    o.x = pkh2(v0.x, v0.y);
    o.y = pkh2(v0.z, v0.w);
    o.z = pkh2(v1.x, v1.y);
    o.w = pkh2(v1.z, v1.w);
    out[i] = o;
}

// ---------------- fp16 mma.sync GEMM, 4 warps, 64x64 warp tiles --------------
// C[M,Nd] = act(A[M,K] @ Bw[K,Nd] + bias); A,Bw fp16; SILU -> fp16 out, else fp32.
template<bool EXPERT, bool GATHER, bool SILU>
__global__ void __launch_bounds__(THREADS, 2) tgemm_k(
    const __half* __restrict__ A, const __half* __restrict__ Bw,
    const float* __restrict__ bias, void* __restrict__ Cm,
    int M, int K, int Nd)
{
    extern __shared__ __half sm[];
    int rowbase = 0;
    if (EXPERT) {
        int e = blockIdx.z;
        M = g_count[e];
        rowbase = g_base[e];
        Bw   += (size_t)e * K * Nd;
        bias += (size_t)e * Nd;
    }
    int m0 = blockIdx.y * BM;
    if (m0 >= M) return;
    int n0 = blockIdx.x * BN;
    int t = threadIdx.x;
    int wid = t >> 5, lane = t & 31;
    int g = lane >> 2, tig = lane & 3;
    int mw = (wid & 1) * 64, nw = (wid >> 1) * 64;
    uint32_t sbase = smem_u32(sm);

    // ---- A cp.async roles: 4 chunks/thread (rows 32 apart); row = 32h = 4x16B
    int ar = t >> 2, aq = t & 3;
    const __half* aptrs[4];
    uint32_t aoffs[4];
    #pragma unroll
    for (int i = 0; i < 4; i++) {
        int r = ar + 32 * i;
        int rr = m0 + r;
        int rc = rr < M ? rr : (M - 1);
        int src = GATHER ? g_row_tok[rowbase + rc] : (EXPERT ? (rowbase + rc) : rc);
        aptrs[i] = A + (size_t)src * K + aq * 8;
        aoffs[i] = (uint32_t)((r * A_ST + aq * 8) * 2);
    }
    // ---- B cp.async roles: 4 chunks/thread (rows 8 apart); row = 128h = 16x16B
    int br = t >> 4, bq = t & 15;
    const __half* bptr = Bw + (size_t)br * Nd + n0 + bq * 8;
    uint32_t boff0 = (uint32_t)((br * B_ST + bq * 8) * 2);

    // ---- ldmatrix lane addresses (half units) ----
    uint32_t laneA = (uint32_t)((mw + (lane & 15)) * A_ST + (lane >> 4) * 8);
    uint32_t laneB = (uint32_t)((((lane >> 3) & 1) * 8 + (lane & 7)) * B_ST
                                + nw + ((lane >> 4) & 1) * 8);

    float c[4][8][4];
    #pragma unroll
    for (int mf = 0; mf < 4; mf++)
        #pragma unroll
        for (int nf = 0; nf < 8; nf++)
            #pragma unroll
            for (int i = 0; i < 4; i++) c[mf][nf][i] = 0.0f;

    int iters = K / BK;

    #pragma unroll
    for (int s = 0; s < 2; s++) {
        uint32_t ab = sbase + s * (ABUF * 2);
        uint32_t bb = sbase + (B_BASE + s * BBUF) * 2;
        int kof = s * BK;
        #pragma unroll
        for (int i = 0; i < 4; i++) cp16(ab + aoffs[i], aptrs[i] + kof);
        #pragma unroll
        for (int i = 0; i < 4; i++)
            cp16(bb + boff0 + i * (8 * B_ST * 2), bptr + (size_t)(kof + 8 * i) * Nd);
        cp_commit();
    }

    for (int it = 0; it < iters; it++) {
        cp_wait<1>();
        __syncthreads();
        if (it + 2 < iters) {
            int s = (it + 2) % 3;
            uint32_t ab = sbase + s * (ABUF * 2);
            uint32_t bb = sbase + (B_BASE + s * BBUF) * 2;
            int kof = (it + 2) * BK;
            #pragma unroll
            for (int i = 0; i < 4; i++) cp16(ab + aoffs[i], aptrs[i] + kof);
            #pragma unroll
            for (int i = 0; i < 4; i++)
                cp16(bb + boff0 + i * (8 * B_ST * 2), bptr + (size_t)(kof + 8 * i) * Nd);
        }
        cp_commit();

        uint32_t Ab = sbase + (it % 3) * (ABUF * 2);
        uint32_t Bb = sbase + (B_BASE + (it % 3) * BBUF) * 2;
        #pragma unroll
        for (int ks = 0; ks < 2; ks++) {    // two k16 steps per BK=32
            uint32_t a[4][4], b[8][2];
            #pragma unroll
            for (int mf = 0; mf < 4; mf++)
                ldsm4(a[mf], Ab + (laneA + mf * 16 * A_ST + ks * 16) * 2);
            #pragma unroll
            for (int np = 0; np < 4; np++) {   // pairs of n8 chunks
                uint32_t r[4];
                ldsm4t(r, Bb + (laneB + ks * 16 * B_ST + np * 16) * 2);
                b[2 * np][0] = r[0]; b[2 * np][1] = r[1];
                b[2 * np + 1][0] = r[2]; b[2 * np + 1][1] = r[3];
            }
            #pragma unroll
            for (int mf = 0; mf < 4; mf++)
                #pragma unroll
                for (int nf = 0; nf < 8; nf++)
                    mma16(c[mf][nf], a[mf], b[nf]);
        }
        __syncthreads();
    }

    // ---- epilogue ----
    int outbase = EXPERT ? rowbase : 0;
    float2 bv[8];
    #pragma unroll
    for (int nf = 0; nf < 8; nf++)
        bv[nf] = *(const float2*)(bias + n0 + nw + nf * 8 + 2 * tig);
    #pragma unroll
    for (int mf = 0; mf < 4; mf++) {
        int row0 = m0 + mw + mf * 16 + g;
        #pragma unroll
        for (int nf = 0; nf < 8; nf++) {
            int col = n0 + nw + nf * 8 + 2 * tig;
            float v0 = c[mf][nf][0] + bv[nf].x, v1 = c[mf][nf][1] + bv[nf].y;
            float v2 = c[mf][nf][2] + bv[nf].x, v3 = c[mf][nf][3] + bv[nf].y;
            if (SILU) {
                v0 = v0 / (1.0f + __expf(-v0));
                v1 = v1 / (1.0f + __expf(-v1));
                v2 = v2 / (1.0f + __expf(-v2));
                v3 = v3 / (1.0f + __expf(-v3));
                __half* Ch = (__half*)Cm;
                if (row0 < M)
                    *(uint32_t*)(Ch + (size_t)(outbase + row0) * Nd + col) = pkh2(v0, v1);
                if (row0 + 8 < M)
                    *(uint32_t*)(Ch + (size_t)(outbase + row0 + 8) * Nd + col) = pkh2(v2, v3);
            } else {
                float* Cf = (float*)Cm;
                if (row0 < M)
                    *(float2*)(Cf + (size_t)(outbase + row0) * Nd + col) = make_float2(v0, v1);
                if (row0 + 8 < M)
                    *(float2*)(Cf + (size_t)(outbase + row0 + 8) * Nd + col) = make_float2(v2, v3);
            }
        }
    }
}

// ---------------- combine ----------------------------------------------------
__global__ void combine_k(const float* __restrict__ y, float* __restrict__ out) {
    int n = blockIdx.x;
    int r0 = g_row_of[n * 2], r1 = g_row_of[n * 2 + 1];
    float w0 = g_tok_w[n * 2], w1 = g_tok_w[n * 2 + 1];
    const float4* y0 = (const float4*)(y + (size_t)r0 * CDIM);
    const float4* y1 = (const float4*)(y + (size_t)r1 * CDIM);
    float4* o = (float4*)(out + (size_t)n * CDIM);
    for (int c = threadIdx.x; c < CDIM / 4; c += blockDim.x) {
        float4 a = y0[c], b = y1[c], v = o[c];
        v.x += w0 * a.x + w1 * b.x;
        v.y += w0 * a.y + w1 * b.y;
        v.z += w0 * a.z + w1 * b.z;
        v.w += w0 * a.w + w1 * b.w;
        o[c] = v;
    }
}

// ---------------- launch -----------------------------------------------------
extern "C" void kernel_launch(void* const* d_in, const int* in_sizes, int n_in,
                              void* d_out, int out_size) {
    const float* x   = (const float*)d_in[0];
    const float* rw1 = (const float*)d_in[1];
    const float* rb1 = (const float*)d_in[2];
    const float* rw2 = (const float*)d_in[3];
    const float* rb2 = (const float*)d_in[4];
    const float* ew1 = (const float*)d_in[5];
    const float* eb1 = (const float*)d_in[6];
    const float* ew2 = (const float*)d_in[7];
    const float* eb2 = (const float*)d_in[8];
    const float* sw1 = (const float*)d_in[9];
    const float* sb1 = (const float*)d_in[10];
    const float* sw2 = (const float*)d_in[11];
    const float* sb2 = (const float*)d_in[12];
    float* out = (float*)d_out;

    __half *xh, *ew1h, *ew2h, *sw1h, *sw2h, *hbufh, *hsh;
    float *ybuf;
    cudaGetSymbolAddress((void**)&xh,    g_xh);
    cudaGetSymbolAddress((void**)&ew1h,  g_ew1h);
    cudaGetSymbolAddress((void**)&ew2h,  g_ew2h);
    cudaGetSymbolAddress((void**)&sw1h,  g_sw1h);
    cudaGetSymbolAddress((void**)&sw2h,  g_sw2h);
    cudaGetSymbolAddress((void**)&hbufh, g_hbufh);
    cudaGetSymbolAddress((void**)&hsh,   g_hsh);
    cudaGetSymbolAddress((void**)&ybuf,  g_ybuf);

    cudaFuncSetAttribute(tgemm_k<false, false, true>,
                         cudaFuncAttributeMaxDynamicSharedMemorySize, SMEM_BYTES);
    cudaFuncSetAttribute(tgemm_k<false, false, false>,
                         cudaFuncAttributeMaxDynamicSharedMemorySize, SMEM_BYTES);
    cudaFuncSetAttribute(tgemm_k<true, true, true>,
                         cudaFuncAttributeMaxDynamicSharedMemorySize, SMEM_BYTES);
    cudaFuncSetAttribute(tgemm_k<true, false, false>,
                         cudaFuncAttributeMaxDynamicSharedMemorySize, SMEM_BYTES);

    init_k<<<1, 32>>>();
    router_k<<<NTOK / 8, 256>>>(x, rw1, rb1, rw2, rb2);
    scan_k<<<1, 32>>>();
    fill_k<<<(NTOK + 255) / 256, 256>>>();

    // fp32 -> fp16 conversions
    {
        auto cvt = [&](const float* in, __half* o, size_t n) {
            int n8 = (int)(n / 8);
            f2h_k<<<(n8 + 255) / 256, 256>>>((const float4*)in, (uint4*)o, n8);
        };
        cvt(x,   xh,   (size_t)NTOK * CDIM);
        cvt(ew1, ew1h, (size_t)NEXP * CDIM * IDIM);
        cvt(ew2, ew2h, (size_t)NEXP * IDIM * CDIM);
        cvt(sw1, sw1h, (size_t)CDIM * IDIM);
        cvt(sw2, sw2h, (size_t)IDIM * CDIM);
    }

    // routed experts
    tgemm_k<true, true, true><<<dim3(IDIM / BN, NTOK / BM, NEXP), THREADS, SMEM_BYTES>>>(
        xh, ew1h, eb1, hbufh, 0, CDIM, IDIM);
    tgemm_k<true, false, false><<<dim3(CDIM / BN, NTOK / BM, NEXP), THREADS, SMEM_BYTES>>>(
        hbufh, ew2h, eb2, ybuf, 0, IDIM, CDIM);

    // shared expert
    tgemm_k<false, false, true><<<dim3(IDIM / BN, NTOK / BM), THREADS, SMEM_BYTES>>>(
        xh, sw1h, sb1, hsh, NTOK, CDIM, IDIM);
    tgemm_k<false, false, false><<<dim3(CDIM / BN, NTOK / BM), THREADS, SMEM_BYTES>>>(
        hsh, sw2h, sb2, out, NTOK, IDIM, CDIM);

    combine_k<<<NTOK, 256>>>(ybuf, out);
}